// round 2
// baseline (speedup 1.0000x reference)
#include <cuda_runtime.h>
#include <cstdint>

#define DIM   512
#define BATCH 32
#define TT    2048
#define G4    2048              // 4*DIM
#define NBLK  128               // persistent blocks for recurrence

// ---------------- device scratch (no allocations allowed) ----------------
__device__ __align__(16) float g_xg[(size_t)TT * G4 * BATCH];   // [t][n][b]
__device__ __align__(16) float g_hbuf[2][DIM * BATCH];          // [k4][b][4]
__device__ unsigned g_flag[NBLK];

typedef unsigned long long ull;

// ---------------- f32x2 helpers ----------------
__device__ __forceinline__ ull f2fma(ull a, ull b, ull c){
    ull d; asm("fma.rn.f32x2 %0, %1, %2, %3;" : "=l"(d) : "l"(a), "l"(b), "l"(c)); return d;
}
__device__ __forceinline__ ull pk2(float lo, float hi){
    ull r; asm("mov.b64 %0, {%1, %2};" : "=l"(r) : "f"(lo), "f"(hi)); return r;
}
__device__ __forceinline__ float2 upk(ull v){
    float2 f; asm("mov.b64 {%0, %1}, %2;" : "=f"(f.x), "=f"(f.y) : "l"(v)); return f;
}
__device__ __forceinline__ float hadd(ull v){ float2 f = upk(v); return f.x + f.y; }

__device__ __forceinline__ float sigf(float x){ return 1.0f / (1.0f + __expf(-x)); }
__device__ __forceinline__ float tanhfast(float x){
    float e = __expf(2.0f * x);              // inf-safe at both ends
    return 1.0f - 2.0f / (e + 1.0f);
}

// =====================================================================
// Kernel 0: init — zero h0 buffer and barrier flags
// =====================================================================
__global__ void init_kernel(){
    int i = blockIdx.x * blockDim.x + threadIdx.x;
    if (i < DIM * BATCH) g_hbuf[0][i] = 0.0f;
    if (i < NBLK) g_flag[i] = 0u;
}

// =====================================================================
// Kernel 1: xg[t][n][b] = sum_k x[b][t][k]*W_ih[n][k] + b_ih[n] + b_hh[n]
// M = 65536 (m = t*32 + b), N = 2048, K = 512. 128x128x8 tile, f32x2.
// =====================================================================
__global__ void __launch_bounds__(256) gemm_xg_kernel(
    const float* __restrict__ x, const float* __restrict__ Wih,
    const float* __restrict__ bih, const float* __restrict__ bhh)
{
    __shared__ float As[8][128];
    __shared__ float Bs[8][128];
    const int tid = threadIdx.x;
    const int bn0 = blockIdx.x * 128;
    const int bm0 = blockIdx.y * 128;
    const int tm0 = (tid >> 4) * 8;
    const int tn0 = (tid & 15) * 8;

    const int lr = tid >> 1;
    const int lk = (tid & 1) * 4;
    const int m  = bm0 + lr;
    const float* ap = x + (size_t)(m & 31) * ((size_t)TT * DIM) + (size_t)(m >> 5) * DIM + lk;
    const float* bp = Wih + (size_t)(bn0 + lr) * DIM + lk;

    ull c2[4][8];
    #pragma unroll
    for (int i = 0; i < 4; i++)
        #pragma unroll
        for (int j = 0; j < 8; j++) c2[i][j] = 0ULL;

    float4 av = *(const float4*)ap;
    float4 bv = *(const float4*)bp;

    for (int k0 = 0; k0 < DIM; k0 += 8){
        As[lk+0][lr]=av.x; As[lk+1][lr]=av.y; As[lk+2][lr]=av.z; As[lk+3][lr]=av.w;
        Bs[lk+0][lr]=bv.x; Bs[lk+1][lr]=bv.y; Bs[lk+2][lr]=bv.z; Bs[lk+3][lr]=bv.w;
        __syncthreads();
        if (k0 + 8 < DIM){                       // prefetch next k-slab
            av = *(const float4*)(ap + k0 + 8);
            bv = *(const float4*)(bp + k0 + 8);
        }
        #pragma unroll
        for (int kk = 0; kk < 8; kk++){
            const ulonglong2* arow = (const ulonglong2*)&As[kk][tm0];
            ulonglong2 a01 = arow[0];            // rows (tm0,tm0+1),(tm0+2,tm0+3)
            ulonglong2 a23 = arow[1];            // rows (tm0+4..7)
            float4 bl = *(const float4*)&Bs[kk][tn0];
            float4 bh = *(const float4*)&Bs[kk][tn0 + 4];
            ull bd[8];
            bd[0]=pk2(bl.x,bl.x); bd[1]=pk2(bl.y,bl.y); bd[2]=pk2(bl.z,bl.z); bd[3]=pk2(bl.w,bl.w);
            bd[4]=pk2(bh.x,bh.x); bd[5]=pk2(bh.y,bh.y); bd[6]=pk2(bh.z,bh.z); bd[7]=pk2(bh.w,bh.w);
            #pragma unroll
            for (int j = 0; j < 8; j++){
                c2[0][j] = f2fma(a01.x, bd[j], c2[0][j]);
                c2[1][j] = f2fma(a01.y, bd[j], c2[1][j]);
                c2[2][j] = f2fma(a23.x, bd[j], c2[2][j]);
                c2[3][j] = f2fma(a23.y, bd[j], c2[3][j]);
            }
        }
        __syncthreads();
    }

    float bias[8];
    #pragma unroll
    for (int j = 0; j < 8; j++){
        int n = bn0 + tn0 + j;
        bias[j] = bih[n] + bhh[n];
    }
    #pragma unroll
    for (int i = 0; i < 8; i++){
        int mg = bm0 + tm0 + i;
        size_t obase = (size_t)(mg >> 5) * ((size_t)G4 * BATCH) + (size_t)(mg & 31);
        #pragma unroll
        for (int j = 0; j < 8; j++){
            float2 p = upk(c2[i >> 1][j]);
            float v = (i & 1) ? p.y : p.x;
            g_xg[obase + (size_t)(bn0 + tn0 + j) * BATCH] = v + bias[j];
        }
    }
}

// =====================================================================
// Kernel 2: persistent recurrence. 128 blocks x 128 threads.
// thread = (b = tid&31, dl = tid>>5); block owns dims dg = bx*4 + dl,
// all 4 gates. W slice + h staged in 96KB dynamic shared. c in regs.
// =====================================================================
__global__ void __launch_bounds__(128) lstm_rec_kernel(
    const float* __restrict__ Whh, float* __restrict__ out)
{
    extern __shared__ float sm[];
    float* shW = sm;                    // [rl = g*4+dl][k]  16*512 = 8192 floats
    float* shH = sm + 16 * DIM;         // [k4][b][4]        16384 floats

    const int tid = threadIdx.x;
    const int b   = tid & 31;
    const int dl  = tid >> 5;
    const int bx  = blockIdx.x;
    const int dg  = bx * 4 + dl;

    // Load this block's 16 W_hh rows into shared (once).
    for (int idx = tid; idx < 2048; idx += 128){       // float4 units
        int rl = idx >> 7;          // 0..15
        int k4 = idx & 127;
        int g = rl >> 2, dloc = rl & 3;
        ((float4*)shW)[idx] =
            ((const float4*)(Whh + (size_t)(g * DIM + bx * 4 + dloc) * DIM))[k4];
    }

    const ulonglong2* w0 = (const ulonglong2*)(shW + (0*4 + dl) * DIM);
    const ulonglong2* w1 = (const ulonglong2*)(shW + (1*4 + dl) * DIM);
    const ulonglong2* w2 = (const ulonglong2*)(shW + (2*4 + dl) * DIM);
    const ulonglong2* w3 = (const ulonglong2*)(shW + (3*4 + dl) * DIM);
    const ulonglong2* hsh = ((const ulonglong2*)shH) + b;   // [k4*32 + b]

    // xg read offsets (coalesced over b)
    const size_t xs = (size_t)G4 * BATCH;
    const float* xg0 = g_xg + (size_t)(0*DIM + dg) * BATCH + b;
    const float* xg1 = g_xg + (size_t)(1*DIM + dg) * BATCH + b;
    const float* xg2 = g_xg + (size_t)(2*DIM + dg) * BATCH + b;
    const float* xg3 = g_xg + (size_t)(3*DIM + dg) * BATCH + b;

    // h write index in [k4][b][4] layout
    const int hwidx = (dg >> 2) * (BATCH * 4) + b * 4 + (dg & 3);
    // deferred out write: this thread owns flat (ob, od)
    const int fo = bx * 128 + tid;
    const int ob = fo >> 9, od = fo & 511;
    const int oshidx = (od >> 2) * (BATCH * 4) + ob * 4 + (od & 3);
    float* outp = out + (size_t)ob * ((size_t)TT * DIM) + od;

    float cc = 0.0f;

    for (int t = 0; t < TT; t++){
        // ---- stage h_{t-1} into shared ----
        const float4* hsrc = (const float4*)g_hbuf[t & 1];
        float4* hdst = (float4*)shH;
        #pragma unroll
        for (int i = 0; i < 32; i++) hdst[tid + i * 128] = hsrc[tid + i * 128];
        __syncthreads();

        // deferred coalesced out write for step t-1
        if (t > 0) outp[(size_t)(t - 1) * DIM] = shH[oshidx];

        // ---- gates = h_{t-1} @ Whh^T (this thread: 4 gates for (b,dg)) ----
        ull a0 = 0ULL, a1 = 0ULL, a2 = 0ULL, a3 = 0ULL;
        #pragma unroll 8
        for (int k4 = 0; k4 < 128; k4++){
            ulonglong2 hv = hsh[k4 * 32];
            ulonglong2 wv;
            wv = w0[k4]; a0 = f2fma(hv.x, wv.x, a0); a0 = f2fma(hv.y, wv.y, a0);
            wv = w1[k4]; a1 = f2fma(hv.x, wv.x, a1); a1 = f2fma(hv.y, wv.y, a1);
            wv = w2[k4]; a2 = f2fma(hv.x, wv.x, a2); a2 = f2fma(hv.y, wv.y, a2);
            wv = w3[k4]; a3 = f2fma(hv.x, wv.x, a3); a3 = f2fma(hv.y, wv.y, a3);
        }
        const size_t xoff = (size_t)t * xs;
        float gi = hadd(a0) + __ldg(xg0 + xoff);
        float gf = hadd(a1) + __ldg(xg1 + xoff);
        float gg = hadd(a2) + __ldg(xg2 + xoff);
        float go = hadd(a3) + __ldg(xg3 + xoff);

        float iv = sigf(gi), fv = sigf(gf), gv = tanhfast(gg), ov = sigf(go);
        cc = fv * cc + iv * gv;
        float hv = ov * tanhfast(cc);
        g_hbuf[(t + 1) & 1][hwidx] = hv;

        // ---- grid barrier (flag array, release/acquire via threadfence) ----
        __threadfence();
        __syncthreads();
        if (tid == 0) *(volatile unsigned*)&g_flag[bx] = (unsigned)(t + 1);
        if (tid < 32){
            const unsigned target = (unsigned)(t + 1);
            volatile unsigned* vf = g_flag;
            for (;;){
                unsigned v0 = vf[tid*4+0], v1 = vf[tid*4+1];
                unsigned v2 = vf[tid*4+2], v3 = vf[tid*4+3];
                bool ok = (v0 >= target) & (v1 >= target) & (v2 >= target) & (v3 >= target);
                if (__all_sync(0xffffffffu, ok)) break;
            }
        }
        __syncthreads();
        __threadfence();
    }

    // final output row: h_{TT-1} sits in g_hbuf[TT & 1] = g_hbuf[0]
    {
        const float4* hsrc = (const float4*)g_hbuf[TT & 1];
        float4* hdst = (float4*)shH;
        #pragma unroll
        for (int i = 0; i < 32; i++) hdst[tid + i * 128] = hsrc[tid + i * 128];
        __syncthreads();
        outp[(size_t)(TT - 1) * DIM] = shH[oshidx];
    }
}

// =====================================================================
extern "C" void kernel_launch(void* const* d_in, const int* in_sizes, int n_in,
                              void* d_out, int out_size)
{
    (void)in_sizes; (void)n_in; (void)out_size;
    const float* x    = (const float*)d_in[0];
    const float* Wih  = (const float*)d_in[1];
    const float* Whh  = (const float*)d_in[2];
    const float* bih  = (const float*)d_in[3];
    const float* bhh  = (const float*)d_in[4];
    float* out = (float*)d_out;

    // 96KB dynamic shared for the persistent kernel (idempotent; attribute
    // persists per-context, so the error-path during capture is harmless).
    static_assert(24576 * sizeof(float) == 98304, "smem size");
    cudaFuncSetAttribute(lstm_rec_kernel,
                         cudaFuncAttributeMaxDynamicSharedMemorySize, 98304);

    init_kernel<<<64, 512>>>();
    dim3 ggrid(G4 / 128, (BATCH * TT) / 128);
    gemm_xg_kernel<<<ggrid, 256>>>(x, Wih, bih, bhh);
    lstm_rec_kernel<<<NBLK, 128, 98304>>>(Whh, out);
}

// round 3
// speedup vs baseline: 2.2937x; 2.2937x over previous
#include <cuda_runtime.h>
#include <cstdint>

#define DIM   512
#define BATCH 32
#define TT    2048
#define G4    2048              // 4*DIM
#define NBLK  128               // persistent blocks for recurrence
#define RTHR  256

// ---------------- device scratch (no allocations allowed) ----------------
__device__ __align__(16) float g_xg[(size_t)TT * G4 * BATCH];   // [t][n][b]
__device__ __align__(16) float g_hbuf[2][DIM * BATCH];          // [k4][b][4]
__device__ unsigned g_count;
__device__ unsigned g_gen;

typedef unsigned long long ull;

// ---------------- f32x2 helpers ----------------
__device__ __forceinline__ ull f2fma(ull a, ull b, ull c){
    ull d; asm("fma.rn.f32x2 %0, %1, %2, %3;" : "=l"(d) : "l"(a), "l"(b), "l"(c)); return d;
}
__device__ __forceinline__ ull f2add(ull a, ull b){
    ull d; asm("add.rn.f32x2 %0, %1, %2;" : "=l"(d) : "l"(a), "l"(b)); return d;
}
__device__ __forceinline__ ull pk2(float lo, float hi){
    ull r; asm("mov.b64 %0, {%1, %2};" : "=l"(r) : "f"(lo), "f"(hi)); return r;
}
__device__ __forceinline__ float2 upk(ull v){
    float2 f; asm("mov.b64 {%0, %1}, %2;" : "=f"(f.x), "=f"(f.y) : "l"(v)); return f;
}
__device__ __forceinline__ float hadd(ull v){ float2 f = upk(v); return f.x + f.y; }

__device__ __forceinline__ float sigf(float x){ return 1.0f / (1.0f + __expf(-x)); }
__device__ __forceinline__ float tanhfast(float x){
    float e = __expf(2.0f * x);              // inf-safe at both ends
    return 1.0f - 2.0f / (e + 1.0f);
}

// ---------------- barrier atomics (PTX scoped semantics) ----------------
__device__ __forceinline__ unsigned atom_add_acqrel(unsigned* p, unsigned v){
    unsigned old;
    asm volatile("atom.acq_rel.gpu.global.add.u32 %0, [%1], %2;"
                 : "=r"(old) : "l"(p), "r"(v) : "memory");
    return old;
}
__device__ __forceinline__ void st_release(unsigned* p, unsigned v){
    asm volatile("st.release.gpu.global.u32 [%0], %1;" :: "l"(p), "r"(v) : "memory");
}
__device__ __forceinline__ unsigned ld_acquire(unsigned* p){
    unsigned v;
    asm volatile("ld.acquire.gpu.global.u32 %0, [%1];" : "=r"(v) : "l"(p) : "memory");
    return v;
}

// =====================================================================
// Kernel 1: xg[t][n][b] = sum_k x[b][t][k]*W_ih[n][k] + b_ih[n] + b_hh[n]
// M = 65536 (m = t*32 + b), N = 2048, K = 512. 128x128x8 tile, f32x2.
// Conflict-free Bs reads: thread columns = c4 + {0..3} and c4+64+{0..3}.
// Also performs one-time init of recurrence state (block (0,0)).
// =====================================================================
__global__ void __launch_bounds__(256) gemm_xg_kernel(
    const float* __restrict__ x, const float* __restrict__ Wih,
    const float* __restrict__ bih, const float* __restrict__ bhh)
{
    __shared__ float As[8][128];
    __shared__ float Bs[8][128];
    const int tid = threadIdx.x;

    if (blockIdx.x == 0 && blockIdx.y == 0){     // fold init (runs before rec)
        for (int i = tid; i < DIM * BATCH; i += 256) g_hbuf[0][i] = 0.0f;
        if (tid == 0){ g_count = 0u; g_gen = 0u; }
    }

    const int bn0 = blockIdx.x * 128;
    const int bm0 = blockIdx.y * 128;
    const int tm0 = (tid >> 4) * 8;
    const int c4  = (tid & 15) * 4;

    const int lr = tid >> 1;
    const int lk = (tid & 1) * 4;
    const int m  = bm0 + lr;
    const float* ap = x + (size_t)(m & 31) * ((size_t)TT * DIM) + (size_t)(m >> 5) * DIM + lk;
    const float* bp = Wih + (size_t)(bn0 + lr) * DIM + lk;

    ull c2[4][8];
    #pragma unroll
    for (int i = 0; i < 4; i++)
        #pragma unroll
        for (int j = 0; j < 8; j++) c2[i][j] = 0ULL;

    float4 av = *(const float4*)ap;
    float4 bv = *(const float4*)bp;

    for (int k0 = 0; k0 < DIM; k0 += 8){
        As[lk+0][lr]=av.x; As[lk+1][lr]=av.y; As[lk+2][lr]=av.z; As[lk+3][lr]=av.w;
        Bs[lk+0][lr]=bv.x; Bs[lk+1][lr]=bv.y; Bs[lk+2][lr]=bv.z; Bs[lk+3][lr]=bv.w;
        __syncthreads();
        if (k0 + 8 < DIM){                       // prefetch next k-slab
            av = *(const float4*)(ap + k0 + 8);
            bv = *(const float4*)(bp + k0 + 8);
        }
        #pragma unroll
        for (int kk = 0; kk < 8; kk++){
            const ulonglong2* arow = (const ulonglong2*)&As[kk][tm0];
            ulonglong2 a01 = arow[0];            // rows (tm0..tm0+3)
            ulonglong2 a23 = arow[1];            // rows (tm0+4..tm0+7)
            float4 bl = *(const float4*)&Bs[kk][c4];        // conflict-free
            float4 bh = *(const float4*)&Bs[kk][c4 + 64];   // conflict-free
            ull bd[8];
            bd[0]=pk2(bl.x,bl.x); bd[1]=pk2(bl.y,bl.y); bd[2]=pk2(bl.z,bl.z); bd[3]=pk2(bl.w,bl.w);
            bd[4]=pk2(bh.x,bh.x); bd[5]=pk2(bh.y,bh.y); bd[6]=pk2(bh.z,bh.z); bd[7]=pk2(bh.w,bh.w);
            #pragma unroll
            for (int j = 0; j < 8; j++){
                c2[0][j] = f2fma(a01.x, bd[j], c2[0][j]);
                c2[1][j] = f2fma(a01.y, bd[j], c2[1][j]);
                c2[2][j] = f2fma(a23.x, bd[j], c2[2][j]);
                c2[3][j] = f2fma(a23.y, bd[j], c2[3][j]);
            }
        }
        __syncthreads();
    }

    float bias[8];
    #pragma unroll
    for (int j = 0; j < 8; j++){
        int n = bn0 + c4 + (j & 3) + ((j >> 2) << 6);
        bias[j] = bih[n] + bhh[n];
    }
    #pragma unroll
    for (int i = 0; i < 8; i++){
        int mg = bm0 + tm0 + i;
        size_t obase = (size_t)(mg >> 5) * ((size_t)G4 * BATCH) + (size_t)(mg & 31);
        #pragma unroll
        for (int j = 0; j < 8; j++){
            float2 p = upk(c2[i >> 1][j]);
            float v = (i & 1) ? p.y : p.x;
            int n = bn0 + c4 + (j & 3) + ((j >> 2) << 6);
            g_xg[obase + (size_t)n * BATCH] = v + bias[j];
        }
    }
}

// =====================================================================
// Kernel 2: persistent recurrence. 128 blocks x 256 threads.
// thread = (b = tid&31, dl = (tid>>5)&3, kh = tid>>7). Block owns dims
// dg = bx*4 + dl (4 gates each); k split in half across kh; pairwise
// shared-mem reduction. W slice + h + reduction buf in 100KB shared.
// c kept in registers by kh==0 threads.
// =====================================================================
__global__ void __launch_bounds__(RTHR) lstm_rec_kernel(
    const float* __restrict__ Whh, float* __restrict__ out)
{
    extern __shared__ float sm[];
    float* shW = sm;                    // [rl = g*4+dl][k]  16*512 = 8192 floats (32KB)
    float* shH = sm + 16 * DIM;         // [k4][b][4]        16384 floats (64KB)
    ull*   shR = (ull*)(shH + 16384);   // reduction: 128 thr * 4 ull  (4KB)

    const int tid = threadIdx.x;
    const int b   = tid & 31;
    const int dl  = (tid >> 5) & 3;
    const int kh  = tid >> 7;           // 0 or 1
    const int bx  = blockIdx.x;
    const int dg  = bx * 4 + dl;

    // Load this block's 16 W_hh rows into shared (once).
    for (int idx = tid; idx < 2048; idx += RTHR){      // float4 units
        int rl = idx >> 7;          // 0..15 = g*4 + dloc
        int k4 = idx & 127;
        int g = rl >> 2, dloc = rl & 3;
        ((float4*)shW)[idx] =
            ((const float4*)(Whh + (size_t)(g * DIM + bx * 4 + dloc) * DIM))[k4];
    }

    // per-thread k-half base: k in [kh*256, kh*256+256) -> 64 k4 chunks
    const ulonglong2* w0 = (const ulonglong2*)(shW + (0*4 + dl) * DIM + kh * 256);
    const ulonglong2* w1 = (const ulonglong2*)(shW + (1*4 + dl) * DIM + kh * 256);
    const ulonglong2* w2 = (const ulonglong2*)(shW + (2*4 + dl) * DIM + kh * 256);
    const ulonglong2* w3 = (const ulonglong2*)(shW + (3*4 + dl) * DIM + kh * 256);
    const ulonglong2* hp = ((const ulonglong2*)shH) + kh * 2048 + b;

    // xg read offsets (coalesced over b)
    const size_t xs = (size_t)G4 * BATCH;
    const float* xg0 = g_xg + (size_t)(0*DIM + dg) * BATCH + b;
    const float* xg1 = g_xg + (size_t)(1*DIM + dg) * BATCH + b;
    const float* xg2 = g_xg + (size_t)(2*DIM + dg) * BATCH + b;
    const float* xg3 = g_xg + (size_t)(3*DIM + dg) * BATCH + b;

    // h write index in [k4][b][4] layout (kh==0 threads own the state)
    const int hwidx = (dg >> 2) * (BATCH * 4) + b * 4 + (dg & 3);
    // deferred out write: first 128 threads own flat (ob, od)
    const int fo = bx * 128 + (tid & 127);
    const int ob = fo >> 9, od = fo & 511;
    const int oshidx = (od >> 2) * (BATCH * 4) + ob * 4 + (od & 3);
    float* outp = out + (size_t)ob * ((size_t)TT * DIM) + od;

    float cc = 0.0f;

    for (int t = 0; t < TT; t++){
        // prefetch xg for this step (independent of h; overlaps everything)
        const size_t xoff = (size_t)t * xs;
        float xv0 = __ldg(xg0 + xoff);
        float xv1 = __ldg(xg1 + xoff);
        float xv2 = __ldg(xg2 + xoff);
        float xv3 = __ldg(xg3 + xoff);

        // ---- stage h_{t-1} into shared ----
        const float4* hsrc = (const float4*)g_hbuf[t & 1];
        float4* hdst = (float4*)shH;
        #pragma unroll
        for (int i = 0; i < 16; i++) hdst[tid + i * RTHR] = hsrc[tid + i * RTHR];
        __syncthreads();

        // deferred coalesced out write for step t-1
        if (t > 0 && tid < 128) outp[(size_t)(t - 1) * DIM] = shH[oshidx];

        // ---- partial gates over this thread's k-half ----
        ull a0 = 0ULL, a1 = 0ULL, a2 = 0ULL, a3 = 0ULL;
        #pragma unroll 4
        for (int k4 = 0; k4 < 64; k4++){
            ulonglong2 hv = hp[k4 * 32];
            ulonglong2 wv;
            wv = w0[k4]; a0 = f2fma(hv.x, wv.x, a0); a0 = f2fma(hv.y, wv.y, a0);
            wv = w1[k4]; a1 = f2fma(hv.x, wv.x, a1); a1 = f2fma(hv.y, wv.y, a1);
            wv = w2[k4]; a2 = f2fma(hv.x, wv.x, a2); a2 = f2fma(hv.y, wv.y, a2);
            wv = w3[k4]; a3 = f2fma(hv.x, wv.x, a3); a3 = f2fma(hv.y, wv.y, a3);
        }

        // ---- pairwise k reduction (kh==1 -> shared, kh==0 adds) ----
        if (kh){
            ull* r = shR + (size_t)(tid & 127) * 4;
            r[0] = a0; r[1] = a1; r[2] = a2; r[3] = a3;
        }
        __syncthreads();
        if (!kh){
            const ull* r = shR + (size_t)tid * 4;
            a0 = f2add(a0, r[0]); a1 = f2add(a1, r[1]);
            a2 = f2add(a2, r[2]); a3 = f2add(a3, r[3]);

            float gi = hadd(a0) + xv0;
            float gf = hadd(a1) + xv1;
            float gg = hadd(a2) + xv2;
            float go = hadd(a3) + xv3;

            float iv = sigf(gi), fv = sigf(gf), gv = tanhfast(gg), ov = sigf(go);
            cc = fv * cc + iv * gv;
            float hv = ov * tanhfast(cc);
            g_hbuf[(t + 1) & 1][hwidx] = hv;
        }

        // ---- grid barrier: arrival counter + generation broadcast ----
        __syncthreads();                       // h stores done block-wide
        if (tid == 0){
            unsigned prev = atom_add_acqrel(&g_count, 1u);
            const unsigned target = (unsigned)(t + 1) * NBLK;
            if (prev == target - 1u){
                st_release(&g_gen, (unsigned)(t + 1));
            } else {
                while (ld_acquire(&g_gen) < (unsigned)(t + 1)) { }
            }
        }
        __syncthreads();
    }

    // final output row: h_{TT-1} sits in g_hbuf[TT & 1] = g_hbuf[0]
    {
        const float4* hsrc = (const float4*)g_hbuf[TT & 1];
        float4* hdst = (float4*)shH;
        #pragma unroll
        for (int i = 0; i < 16; i++) hdst[tid + i * RTHR] = hsrc[tid + i * RTHR];
        __syncthreads();
        if (tid < 128) outp[(size_t)(TT - 1) * DIM] = shH[oshidx];
    }
}

// =====================================================================
extern "C" void kernel_launch(void* const* d_in, const int* in_sizes, int n_in,
                              void* d_out, int out_size)
{
    (void)in_sizes; (void)n_in; (void)out_size;
    const float* x    = (const float*)d_in[0];
    const float* Wih  = (const float*)d_in[1];
    const float* Whh  = (const float*)d_in[2];
    const float* bih  = (const float*)d_in[3];
    const float* bhh  = (const float*)d_in[4];
    float* out = (float*)d_out;

    // shW 32KB + shH 64KB + shR 4KB = 102400 bytes dynamic shared
    cudaFuncSetAttribute(lstm_rec_kernel,
                         cudaFuncAttributeMaxDynamicSharedMemorySize, 102400);

    dim3 ggrid(G4 / 128, (BATCH * TT) / 128);
    gemm_xg_kernel<<<ggrid, 256>>>(x, Wih, bih, bhh);
    lstm_rec_kernel<<<NBLK, RTHR, 102400>>>(Whh, out);
}